// round 1
// baseline (speedup 1.0000x reference)
#include <cuda_runtime.h>

// Fused autoencoder forward + analytic/forward-mode Jacobians.
// Outputs (concatenated fp32): theta[N,2] | J_h[N,2,2] | q_hat[N,2] | J_h_dec[N,2,2] | J_h_ana[N,2,2]

__device__ __forceinline__ void act(float z, float& h, float& s) {
    // softplus (numerically stable, matches jax.nn.softplus) and sigmoid
    float az = fabsf(z);
    float t  = __expf(-az);            // MUFU.EX2
    float u  = 1.0f + t;
    float r  = __fdividef(1.0f, u);    // MUFU.RCP (approx)
    h = fmaxf(z, 0.0f) + __logf(u);    // MUFU.LG2
    s = (z >= 0.0f) ? r : t * r;
}

// MLP 2 -> 16 -> 16 -> 2 with softplus; returns outputs and full 2x2 Jacobian
// via forward-mode tangent propagation of the two input basis vectors.
// Layer 3 is fused into 6 accumulators (no second hidden array -> fewer regs).
__device__ __forceinline__ void mlp_jac(
    float x0, float x1,
    const float* __restrict__ W1, const float* __restrict__ B1,
    const float* __restrict__ W2, const float* __restrict__ B2,
    const float* __restrict__ W3, const float* __restrict__ B3,
    float& y0, float& y1,
    float& J00, float& J01, float& J10, float& J11)
{
    float h[16], ta[16], tb[16];
#pragma unroll
    for (int i = 0; i < 16; ++i) {
        float w0 = W1[2 * i];
        float w1 = W1[2 * i + 1];
        float z  = fmaf(w0, x0, fmaf(w1, x1, B1[i]));
        float hh, s;
        act(z, hh, s);
        h[i]  = hh;
        ta[i] = s * w0;   // tangent wrt x0
        tb[i] = s * w1;   // tangent wrt x1
    }

    float acc0 = B3[0], acc1 = B3[1];
    float j00 = 0.f, j01 = 0.f, j10 = 0.f, j11 = 0.f;
#pragma unroll
    for (int j = 0; j < 16; ++j) {
        float z = B2[j], a = 0.f, b = 0.f;
#pragma unroll
        for (int i = 0; i < 16; ++i) {
            float w = W2[16 * j + i];
            z = fmaf(w, h[i],  z);
            a = fmaf(w, ta[i], a);
            b = fmaf(w, tb[i], b);
        }
        float hh, s;
        act(z, hh, s);
        float sa = s * a;
        float sb = s * b;
        float w30 = W3[j];        // W3 row 0 (out 0)
        float w31 = W3[16 + j];   // W3 row 1 (out 1)
        acc0 = fmaf(w30, hh, acc0);
        acc1 = fmaf(w31, hh, acc1);
        j00  = fmaf(w30, sa, j00);
        j01  = fmaf(w30, sb, j01);
        j10  = fmaf(w31, sa, j10);
        j11  = fmaf(w31, sb, j11);
    }
    y0 = acc0; y1 = acc1;
    J00 = j00; J01 = j01; J10 = j10; J11 = j11;
}

__global__ void __launch_bounds__(256) ae_kernel(
    const float* __restrict__ q,
    const float* __restrict__ ew1, const float* __restrict__ eb1,
    const float* __restrict__ ew2, const float* __restrict__ eb2,
    const float* __restrict__ ew3, const float* __restrict__ eb3,
    const float* __restrict__ dw1, const float* __restrict__ db1,
    const float* __restrict__ dw2, const float* __restrict__ db2,
    const float* __restrict__ dw3, const float* __restrict__ db3,
    float* __restrict__ out, int N)
{
    // Shared weight staging: 708 floats total (uniform broadcast reads later).
    __shared__ float sm[708];
    float* s_ew1 = sm +   0;  // 32
    float* s_eb1 = sm +  32;  // 16
    float* s_ew2 = sm +  48;  // 256
    float* s_eb2 = sm + 304;  // 16
    float* s_ew3 = sm + 320;  // 32
    float* s_eb3 = sm + 352;  // 2
    float* s_dw1 = sm + 354;  // 32
    float* s_db1 = sm + 386;  // 16
    float* s_dw2 = sm + 402;  // 256
    float* s_db2 = sm + 658;  // 16
    float* s_dw3 = sm + 674;  // 32
    float* s_db3 = sm + 706;  // 2

    const int t = threadIdx.x;
    if (t < 32) {
        s_ew1[t] = ew1[t];
        s_dw1[t] = dw1[t];
        s_ew3[t] = ew3[t];
        s_dw3[t] = dw3[t];
    } else if (t < 48) {
        int i = t - 32;
        s_eb1[i] = eb1[i];
        s_db1[i] = db1[i];
        s_eb2[i] = eb2[i];
        s_db2[i] = db2[i];
    } else if (t == 48) {
        s_eb3[0] = eb3[0]; s_eb3[1] = eb3[1];
        s_db3[0] = db3[0]; s_db3[1] = db3[1];
    }
    s_ew2[t] = ew2[t];   // blockDim == 256, one element each
    s_dw2[t] = dw2[t];
    __syncthreads();

    const int n = blockIdx.x * 256 + t;
    if (n >= N) return;

    const float2 qv = reinterpret_cast<const float2*>(q)[n];
    const float q0 = qv.x, q1 = qv.y;

    // Analytic Jacobian:
    //   theta0 = atan2(q1, q0): d/dq0 = -q1/r2, d/dq1 = q0/r2 (no eps, like jax)
    //   theta1 = sqrt(r2 + 1e-8): d/dq = q / sqrt(r2 + 1e-8)
    const float r2  = fmaf(q0, q0, q1 * q1);
    const float inv = __fdividef(1.0f, r2);
    const float isr = rsqrtf(r2 + 1e-8f);
    const float ja00 = -q1 * inv;
    const float ja01 =  q0 * inv;
    const float ja10 =  q0 * isr;
    const float ja11 =  q1 * isr;

    // Encoder: theta = enc(q), J_h = d theta / d q
    float th0, th1, jh00, jh01, jh10, jh11;
    mlp_jac(q0, q1, s_ew1, s_eb1, s_ew2, s_eb2, s_ew3, s_eb3,
            th0, th1, jh00, jh01, jh10, jh11);

    // Decoder: q_hat = dec(theta), J_h_dec = d dec / d theta at theta
    float qh0, qh1, jd00, jd01, jd10, jd11;
    mlp_jac(th0, th1, s_dw1, s_db1, s_dw2, s_db2, s_dw3, s_db3,
            qh0, qh1, jd00, jd01, jd10, jd11);

    // Coalesced stores into the 5 concatenated output sections.
    const size_t Ns = (size_t)N;
    float2* o_theta = reinterpret_cast<float2*>(out);
    float4* o_jh    = reinterpret_cast<float4*>(out + 2 * Ns);
    float2* o_qhat  = reinterpret_cast<float2*>(out + 6 * Ns);
    float4* o_jd    = reinterpret_cast<float4*>(out + 8 * Ns);
    float4* o_ja    = reinterpret_cast<float4*>(out + 12 * Ns);

    o_theta[n] = make_float2(th0, th1);
    o_jh[n]    = make_float4(jh00, jh01, jh10, jh11);
    o_qhat[n]  = make_float2(qh0, qh1);
    o_jd[n]    = make_float4(jd00, jd01, jd10, jd11);
    o_ja[n]    = make_float4(ja00, ja01, ja10, ja11);
}

extern "C" void kernel_launch(void* const* d_in, const int* in_sizes, int n_in,
                              void* d_out, int out_size) {
    const float* q   = (const float*)d_in[0];
    const float* ew1 = (const float*)d_in[1];
    const float* eb1 = (const float*)d_in[2];
    const float* ew2 = (const float*)d_in[3];
    const float* eb2 = (const float*)d_in[4];
    const float* ew3 = (const float*)d_in[5];
    const float* eb3 = (const float*)d_in[6];
    const float* dw1 = (const float*)d_in[7];
    const float* db1 = (const float*)d_in[8];
    const float* dw2 = (const float*)d_in[9];
    const float* db2 = (const float*)d_in[10];
    const float* dw3 = (const float*)d_in[11];
    const float* db3 = (const float*)d_in[12];

    const int N = in_sizes[0] / 2;
    const int blocks = (N + 255) / 256;
    ae_kernel<<<blocks, 256>>>(q, ew1, eb1, ew2, eb2, ew3, eb3,
                               dw1, db1, dw2, db2, dw3, db3,
                               (float*)d_out, N);
}